// round 8
// baseline (speedup 1.0000x reference)
#include <cuda_runtime.h>
#include <cuda_fp16.h>
#include <cstdint>

// ---------------------------------------------------------------- problem dims
#define BB   8
#define CC   256
#define HH   64
#define WW   64
#define OO   256
#define TAPS 9
#define KTOT (CC * TAPS)        // 2304
#define PIXI (HH * WW)          // 4096
#define TILE_P 64               // pixels per CTA
#define BKC  32                 // channels per K-chunk
#define NCHUNK (TAPS * (CC / BKC))  // 72
#define NTH  256

// ---------------------------------------------------------------- scratch
__device__ __half   g_x_nhwc[(size_t)BB * PIXI * CC];      // [b][pix][c] fp16
__device__ uint32_t g_wtf[(size_t)OO * KTOT / 2];          // A-frag-major fp16 pairs

// ---------------------------------------------------------------- smem layout
// A: 2 bufs x [2 ksteps][16 otiles][32 lanes][4 u32] = 2 x 16384
// B: 2 bufs x [2 ksteps][ 8 ntiles][32 lanes][2 u32] = 2 x  4096
#define SM_A   0
#define SM_B   (SM_A + 2 * 16384)            // 32768
#define SM_CW  (SM_B + 2 * 4096)             // 40960
#define SM_CI  (SM_CW + TAPS * TILE_P * 16)  // 50176
#define SMEM_SZ (SM_CI + TAPS * TILE_P * 8)  // 54784

// ---------------------------------------------------------------- helpers
__device__ __forceinline__ uint32_t smem_u32(const void* p) {
    uint32_t a;
    asm("{ .reg .u64 t; cvta.to.shared.u64 t, %1; cvt.u32.u64 %0, t; }" : "=r"(a) : "l"(p));
    return a;
}
#define CP_ASYNC16(sa, ga) \
    asm volatile("cp.async.cg.shared.global [%0], [%1], 16;" :: "r"(sa), "l"(ga))
#define CP_COMMIT() asm volatile("cp.async.commit_group;" ::: "memory")
#define CP_WAIT0()  asm volatile("cp.async.wait_group 0;" ::: "memory")

__device__ __forceinline__ void mma_f16(float* d, const uint32_t* a, const uint32_t* b) {
    asm volatile(
        "mma.sync.aligned.m16n8k16.row.col.f32.f16.f16.f32 "
        "{%0,%1,%2,%3}, {%4,%5,%6,%7}, {%8,%9}, {%0,%1,%2,%3};"
        : "+f"(d[0]), "+f"(d[1]), "+f"(d[2]), "+f"(d[3])
        : "r"(a[0]), "r"(a[1]), "r"(a[2]), "r"(a[3]), "r"(b[0]), "r"(b[1]));
}

// ---------------------------------------------------------------- fused prep
#define XBLKS 2048
#define WBLKS ((OO * KTOT / 2) / 256)   // 1152

__global__ void __launch_bounds__(256)
prep_kernel(const float* __restrict__ x, const float* __restrict__ w) {
    const int bid = blockIdx.x;
    const int tid = threadIdx.x;

    if (bid < XBLKS) {
        __shared__ float tile[64][65];
        const int p0 = (bid >> 2) * 64;
        const int c0 = (bid & 3) * 64;
        const int b  = p0 >> 12;
        const int pimg0 = p0 & 4095;
        {
            const int cl  = tid >> 2;
            const int sp  = (tid & 3) * 16;
            const float* src = x + ((size_t)(b * CC + c0 + cl)) * PIXI + pimg0 + sp;
            #pragma unroll
            for (int j = 0; j < 4; j++) {
                const float4 v = *reinterpret_cast<const float4*>(src + j * 4);
                tile[cl][sp + j * 4 + 0] = v.x;
                tile[cl][sp + j * 4 + 1] = v.y;
                tile[cl][sp + j * 4 + 2] = v.z;
                tile[cl][sp + j * 4 + 3] = v.w;
            }
        }
        __syncthreads();
        {
            const int pl = tid >> 2;
            const int cs = (tid & 3) * 16;
            uint32_t packed[8];
            #pragma unroll
            for (int j = 0; j < 8; j++) {
                const __half2 h = __float22half2_rn(
                    make_float2(tile[cs + j * 2][pl], tile[cs + j * 2 + 1][pl]));
                packed[j] = *reinterpret_cast<const uint32_t*>(&h);
            }
            uint32_t* dst = reinterpret_cast<uint32_t*>(
                g_x_nhwc + ((size_t)(p0 + pl)) * CC + c0 + cs);
            *reinterpret_cast<uint4*>(dst)     = make_uint4(packed[0], packed[1], packed[2], packed[3]);
            *reinterpret_cast<uint4*>(dst + 4) = make_uint4(packed[4], packed[5], packed[6], packed[7]);
        }
    } else {
        const int i = (bid - XBLKS) * 256 + tid;
        const int reg   = i & 3;
        const int lane  = (i >> 2) & 31;
        const int otile = (i >> 7) & 15;
        const int s     = (i >> 11) & 1;
        const int ck    = i >> 12;
        const int o   = otile * 16 + (lane >> 2) + (reg & 1) * 8;
        const int k16 = (lane & 3) * 2 + (reg >> 1) * 8;
        const int c   = (ck & 7) * 32 + s * 16 + k16;
        const int tap = ck >> 3;
        const float v0 = w[((size_t)(o * CC + c + 0)) * TAPS + tap];
        const float v1 = w[((size_t)(o * CC + c + 1)) * TAPS + tap];
        const __half2 h = __float22half2_rn(make_float2(v0, v1));
        g_wtf[i] = *reinterpret_cast<const uint32_t*>(&h);
    }
}

// ---------------------------------------------------------------- main kernel
__global__ void __launch_bounds__(NTH, 2)
dfconv_main(const float* __restrict__ offset, float* __restrict__ out) {
    extern __shared__ char smem[];
    const int tid  = threadIdx.x;
    const int wid  = tid >> 5;
    const int lane = tid & 31;

    const int b     = blockIdx.x >> 6;           // 64 tiles per batch
    const int pimg0 = (blockIdx.x & 63) * TILE_P;

    float4*  cw = reinterpret_cast<float4*>(smem + SM_CW);
    ushort4* ci = reinterpret_cast<ushort4*>(smem + SM_CI);

    // ---- bilinear coefficients: 9 taps x 64 pixels
    for (int t = tid; t < TAPS * TILE_P; t += NTH) {
        const int k = t >> 6;                    // /TILE_P
        const int p = t & 63;
        const int pimg = pimg0 + p;
        const int h = pimg >> 6;
        const int w = pimg & 63;
        const int ky = k / 3;
        const int kx = k - ky * 3;
        const float dy = offset[((size_t)(b * 18 + k * 2 + 0)) * PIXI + pimg];
        const float dx = offset[((size_t)(b * 18 + k * 2 + 1)) * PIXI + pimg];
        const float py = (float)(h - 1 + ky) + dy;
        const float px = (float)(w - 1 + kx) + dx;
        const float y0f = floorf(py);
        const float x0f = floorf(px);
        const float fy = py - y0f;
        const float fx = px - x0f;
        const int y0 = (int)y0f;
        const int x0 = (int)x0f;
        const bool vy0 = (y0 >= 0) && (y0 <= HH - 1);
        const bool vy1 = (y0 + 1 >= 0) && (y0 + 1 <= HH - 1);
        const bool vx0 = (x0 >= 0) && (x0 <= WW - 1);
        const bool vx1 = (x0 + 1 >= 0) && (x0 + 1 <= WW - 1);
        float4 wv;
        wv.x = (vy0 && vx0) ? (1.f - fy) * (1.f - fx) : 0.f;
        wv.y = (vy0 && vx1) ? (1.f - fy) * fx         : 0.f;
        wv.z = (vy1 && vx0) ? fy * (1.f - fx)         : 0.f;
        wv.w = (vy1 && vx1) ? fy * fx                 : 0.f;
        const int yc0 = min(max(y0,     0), HH - 1);
        const int yc1 = min(max(y0 + 1, 0), HH - 1);
        const int xc0 = min(max(x0,     0), WW - 1);
        const int xc1 = min(max(x0 + 1, 0), WW - 1);
        ushort4 iv;
        iv.x = (unsigned short)(yc0 * WW + xc0);
        iv.y = (unsigned short)(yc0 * WW + xc1);
        iv.z = (unsigned short)(yc1 * WW + xc0);
        iv.w = (unsigned short)(yc1 * WW + xc1);
        cw[t] = wv;
        ci[t] = iv;
    }

    const __half* xb = g_x_nhwc + (size_t)b * PIXI * CC;
    const int seg = tid & 3;                 // 8-channel segment
    const int p   = tid >> 2;                // pixel 0..63
    const int rsel = seg & 1;
    const int sblk = (seg >> 1) * 8;         // kstep offset in ntile units
    const int bbase = ((sblk + (p >> 3)) * 32 + (p & 7) * 4) * 2 + rsel;
    const __half* xc = xb + seg * 8;

    uint4 gr0, gr1, gr2, gr3;
    float4 gwv;

    auto gather_load = [&](int ck) {
        const int tap = ck >> 3;
        const int c0  = (ck & 7) * BKC;
        gwv = cw[tap * TILE_P + p];
        const ushort4 iv = ci[tap * TILE_P + p];
        const __half* xcc = xc + c0;
        gr0 = *reinterpret_cast<const uint4*>(xcc + (int)iv.x * CC);
        gr1 = *reinterpret_cast<const uint4*>(xcc + (int)iv.y * CC);
        gr2 = *reinterpret_cast<const uint4*>(xcc + (int)iv.z * CC);
        gr3 = *reinterpret_cast<const uint4*>(xcc + (int)iv.w * CC);
    };

    auto gather_store = [&](int bufsel) {
        uint32_t* bb = reinterpret_cast<uint32_t*>(smem + SM_B + bufsel * 4096);
        const __half2 wx2 = __float2half2_rn(gwv.x);
        const __half2 wy2 = __float2half2_rn(gwv.y);
        const __half2 wz2 = __float2half2_rn(gwv.z);
        const __half2 ww2 = __float2half2_rn(gwv.w);
        const __half2* a0 = reinterpret_cast<const __half2*>(&gr0);
        const __half2* a1 = reinterpret_cast<const __half2*>(&gr1);
        const __half2* a2 = reinterpret_cast<const __half2*>(&gr2);
        const __half2* a3 = reinterpret_cast<const __half2*>(&gr3);
        #pragma unroll
        for (int j = 0; j < 4; j++) {
            __half2 s = __hmul2(wx2, a0[j]);
            s = __hfma2(wy2, a1[j], s);
            s = __hfma2(wz2, a2[j], s);
            s = __hfma2(ww2, a3[j], s);
            bb[bbase + j * 2] = *reinterpret_cast<const uint32_t*>(&s);
        }
    };

    // A chunk prefetch: 16 KB, 256 threads x 64 B
    auto a_prefetch = [&](int ck, int bufsel) {
        const uint32_t* src = g_wtf + (size_t)ck * 4096 + tid * 16;
        const uint32_t dst = smem_u32(smem + SM_A + bufsel * 16384) + tid * 64;
        CP_ASYNC16(dst,      src);
        CP_ASYNC16(dst + 16, src + 4);
        CP_ASYNC16(dst + 32, src + 8);
        CP_ASYNC16(dst + 48, src + 12);
        CP_COMMIT();
    };

    // ---- prologue
    a_prefetch(0, 0);
    __syncthreads();
    gather_load(0);
    gather_store(0);
    CP_WAIT0();
    __syncthreads();

    const int warp_m = wid >> 1;   // 0..3 -> 64 output rows
    const int warp_n = wid & 1;    // 0..1 -> 32 pixels

    float acc[4][4][4];
    #pragma unroll
    for (int mf = 0; mf < 4; mf++)
        #pragma unroll
        for (int nf = 0; nf < 4; nf++)
            #pragma unroll
            for (int r = 0; r < 4; r++)
                acc[mf][nf][r] = 0.f;

    for (int ck = 0; ck < NCHUNK; ck++) {
        const int buf = ck & 1;
        if (ck + 1 < NCHUNK) {
            a_prefetch(ck + 1, buf ^ 1);
            gather_load(ck + 1);       // LDGs in flight during MMA
        }

        const uint32_t* Af = reinterpret_cast<const uint32_t*>(smem + SM_A + buf * 16384);
        const uint32_t* Bf = reinterpret_cast<const uint32_t*>(smem + SM_B + buf * 4096);

        #pragma unroll
        for (int s = 0; s < 2; s++) {
            uint32_t a[4][4];
            uint32_t bq[4][2];
            #pragma unroll
            for (int mf = 0; mf < 4; mf++) {
                const uint4 v = reinterpret_cast<const uint4*>(Af)[(s * 16 + warp_m * 4 + mf) * 32 + lane];
                a[mf][0] = v.x; a[mf][1] = v.y; a[mf][2] = v.z; a[mf][3] = v.w;
            }
            #pragma unroll
            for (int nf = 0; nf < 4; nf++) {
                const uint2 v = reinterpret_cast<const uint2*>(Bf)[(s * 8 + warp_n * 4 + nf) * 32 + lane];
                bq[nf][0] = v.x; bq[nf][1] = v.y;
            }
            #pragma unroll
            for (int mf = 0; mf < 4; mf++)
                #pragma unroll
                for (int nf = 0; nf < 4; nf++)
                    mma_f16(acc[mf][nf], a[mf], bq[nf]);
        }

        if (ck + 1 < NCHUNK) gather_store(buf ^ 1);
        CP_WAIT0();
        __syncthreads();
    }

    // ---- epilogue: direct float2 stores (32B sector-coalesced per lane quad)
    #pragma unroll
    for (int mf = 0; mf < 4; mf++) {
        const int o = warp_m * 64 + mf * 16 + (lane >> 2);
        float* r0 = out + ((size_t)(b * OO + o)) * PIXI + pimg0 + warp_n * 32 + (lane & 3) * 2;
        float* r1 = r0 + 8 * PIXI;
        #pragma unroll
        for (int nf = 0; nf < 4; nf++) {
            *reinterpret_cast<float2*>(r0 + nf * 8) = make_float2(acc[mf][nf][0], acc[mf][nf][1]);
            *reinterpret_cast<float2*>(r1 + nf * 8) = make_float2(acc[mf][nf][2], acc[mf][nf][3]);
        }
    }
}

// ---------------------------------------------------------------- launcher
extern "C" void kernel_launch(void* const* d_in, const int* in_sizes, int n_in,
                              void* d_out, int out_size) {
    const float* x      = (const float*)d_in[0];
    const float* offset = (const float*)d_in[1];
    const float* weight = (const float*)d_in[2];
    float* out          = (float*)d_out;

    cudaFuncSetAttribute(dfconv_main,
                         cudaFuncAttributeMaxDynamicSharedMemorySize, SMEM_SZ);

    prep_kernel<<<XBLKS + WBLKS, 256>>>(x, weight);
    dfconv_main<<<BB * (PIXI / TILE_P), NTH, SMEM_SZ>>>(offset, out);
}

// round 12
// speedup vs baseline: 1.0993x; 1.0993x over previous
#include <cuda_runtime.h>
#include <cuda_fp16.h>
#include <cstdint>

// ---------------------------------------------------------------- problem dims
#define BB   8
#define CC   256
#define HH   64
#define WW   64
#define OO   256
#define TAPS 9
#define KTOT (CC * TAPS)        // 2304
#define PIXI (HH * WW)          // 4096
#define TILE_P 128              // pixels per CTA
#define BKC  32                 // channels per K-chunk
#define NCHUNK (TAPS * (CC / BKC))  // 72
#define NINT  (NCHUNK / 2)          // 36 double-chunk intervals
#define NTH  512

// ---------------------------------------------------------------- scratch
__device__ __half   g_x_nhwc[(size_t)BB * PIXI * CC];      // [b][pix][c] fp16
__device__ uint32_t g_wtf[(size_t)OO * KTOT / 2];          // A-frag-major fp16 pairs

// ---------------------------------------------------------------- smem layout
// A: 2 bufs x 2 chunks x 16KB = 65536
// B: 2 bufs x 2 chunks x  8KB = 32768
#define SM_A   0
#define SM_B   (SM_A + 2 * 32768)            // 65536
#define SM_CW  (SM_B + 2 * 16384)            // 98304
#define SM_CI  (SM_CW + TAPS * TILE_P * 16)  // 116736
#define SMEM_SZ (SM_CI + TAPS * TILE_P * 8)  // 125952

// ---------------------------------------------------------------- helpers
__device__ __forceinline__ uint32_t smem_u32(const void* p) {
    uint32_t a;
    asm("{ .reg .u64 t; cvta.to.shared.u64 t, %1; cvt.u32.u64 %0, t; }" : "=r"(a) : "l"(p));
    return a;
}
#define CP_ASYNC16(sa, ga) \
    asm volatile("cp.async.cg.shared.global [%0], [%1], 16;" :: "r"(sa), "l"(ga))
#define CP_COMMIT() asm volatile("cp.async.commit_group;" ::: "memory")
#define CP_WAIT0()  asm volatile("cp.async.wait_group 0;" ::: "memory")

__device__ __forceinline__ void mma_f16(float* d, const uint32_t* a, const uint32_t* b) {
    asm volatile(
        "mma.sync.aligned.m16n8k16.row.col.f32.f16.f16.f32 "
        "{%0,%1,%2,%3}, {%4,%5,%6,%7}, {%8,%9}, {%0,%1,%2,%3};"
        : "+f"(d[0]), "+f"(d[1]), "+f"(d[2]), "+f"(d[3])
        : "r"(a[0]), "r"(a[1]), "r"(a[2]), "r"(a[3]), "r"(b[0]), "r"(b[1]));
}

// ---------------------------------------------------------------- fused prep
#define XBLKS 2048
#define WBLKS ((OO * KTOT / 2) / 256)   // 1152

__global__ void __launch_bounds__(256)
prep_kernel(const float* __restrict__ x, const float* __restrict__ w) {
    const int bid = blockIdx.x;
    const int tid = threadIdx.x;

    if (bid < XBLKS) {
        __shared__ float tile[64][65];
        const int p0 = (bid >> 2) * 64;
        const int c0 = (bid & 3) * 64;
        const int b  = p0 >> 12;
        const int pimg0 = p0 & 4095;
        {
            const int cl  = tid >> 2;
            const int sp  = (tid & 3) * 16;
            const float* src = x + ((size_t)(b * CC + c0 + cl)) * PIXI + pimg0 + sp;
            #pragma unroll
            for (int j = 0; j < 4; j++) {
                const float4 v = *reinterpret_cast<const float4*>(src + j * 4);
                tile[cl][sp + j * 4 + 0] = v.x;
                tile[cl][sp + j * 4 + 1] = v.y;
                tile[cl][sp + j * 4 + 2] = v.z;
                tile[cl][sp + j * 4 + 3] = v.w;
            }
        }
        __syncthreads();
        {
            const int pl = tid >> 2;
            const int cs = (tid & 3) * 16;
            uint32_t packed[8];
            #pragma unroll
            for (int j = 0; j < 8; j++) {
                const __half2 h = __float22half2_rn(
                    make_float2(tile[cs + j * 2][pl], tile[cs + j * 2 + 1][pl]));
                packed[j] = *reinterpret_cast<const uint32_t*>(&h);
            }
            uint32_t* dst = reinterpret_cast<uint32_t*>(
                g_x_nhwc + ((size_t)(p0 + pl)) * CC + c0 + cs);
            *reinterpret_cast<uint4*>(dst)     = make_uint4(packed[0], packed[1], packed[2], packed[3]);
            *reinterpret_cast<uint4*>(dst + 4) = make_uint4(packed[4], packed[5], packed[6], packed[7]);
        }
    } else {
        const int i = (bid - XBLKS) * 256 + tid;
        const int reg   = i & 3;
        const int lane  = (i >> 2) & 31;
        const int otile = (i >> 7) & 15;
        const int s     = (i >> 11) & 1;
        const int ck    = i >> 12;
        const int o   = otile * 16 + (lane >> 2) + (reg & 1) * 8;
        const int k16 = (lane & 3) * 2 + (reg >> 1) * 8;
        const int c   = (ck & 7) * 32 + s * 16 + k16;
        const int tap = ck >> 3;
        const float v0 = w[((size_t)(o * CC + c + 0)) * TAPS + tap];
        const float v1 = w[((size_t)(o * CC + c + 1)) * TAPS + tap];
        const __half2 h = __float22half2_rn(make_float2(v0, v1));
        g_wtf[i] = *reinterpret_cast<const uint32_t*>(&h);
    }
}

// ---------------------------------------------------------------- main kernel
__global__ void __launch_bounds__(NTH, 1)
dfconv_main(const float* __restrict__ offset, float* __restrict__ out) {
    extern __shared__ char smem[];
    const int tid  = threadIdx.x;
    const int wid  = tid >> 5;
    const int lane = tid & 31;

    const int b     = blockIdx.x >> 5;
    const int pimg0 = (blockIdx.x & 31) * TILE_P;

    float4*  cw = reinterpret_cast<float4*>(smem + SM_CW);
    ushort4* ci = reinterpret_cast<ushort4*>(smem + SM_CI);

    // ---- bilinear coefficients: 9 taps x 128 pixels
    for (int t = tid; t < TAPS * TILE_P; t += NTH) {
        const int k = t >> 7;
        const int p = t & 127;
        const int pimg = pimg0 + p;
        const int h = pimg >> 6;
        const int w = pimg & 63;
        const int ky = k / 3;
        const int kx = k - ky * 3;
        const float dy = offset[((size_t)(b * 18 + k * 2 + 0)) * PIXI + pimg];
        const float dx = offset[((size_t)(b * 18 + k * 2 + 1)) * PIXI + pimg];
        const float py = (float)(h - 1 + ky) + dy;
        const float px = (float)(w - 1 + kx) + dx;
        const float y0f = floorf(py);
        const float x0f = floorf(px);
        const float fy = py - y0f;
        const float fx = px - x0f;
        const int y0 = (int)y0f;
        const int x0 = (int)x0f;
        const bool vy0 = (y0 >= 0) && (y0 <= HH - 1);
        const bool vy1 = (y0 + 1 >= 0) && (y0 + 1 <= HH - 1);
        const bool vx0 = (x0 >= 0) && (x0 <= WW - 1);
        const bool vx1 = (x0 + 1 >= 0) && (x0 + 1 <= WW - 1);
        float4 wv;
        wv.x = (vy0 && vx0) ? (1.f - fy) * (1.f - fx) : 0.f;
        wv.y = (vy0 && vx1) ? (1.f - fy) * fx         : 0.f;
        wv.z = (vy1 && vx0) ? fy * (1.f - fx)         : 0.f;
        wv.w = (vy1 && vx1) ? fy * fx                 : 0.f;
        const int yc0 = min(max(y0,     0), HH - 1);
        const int yc1 = min(max(y0 + 1, 0), HH - 1);
        const int xc0 = min(max(x0,     0), WW - 1);
        const int xc1 = min(max(x0 + 1, 0), WW - 1);
        ushort4 iv;
        iv.x = (unsigned short)(yc0 * WW + xc0);
        iv.y = (unsigned short)(yc0 * WW + xc1);
        iv.z = (unsigned short)(yc1 * WW + xc0);
        iv.w = (unsigned short)(yc1 * WW + xc1);
        cw[t] = wv;
        ci[t] = iv;
    }

    const __half* xb = g_x_nhwc + (size_t)b * PIXI * CC;
    const int seg = tid & 3;                 // 8-channel segment
    const int p   = tid >> 2;                // pixel 0..127
    const int rsel = seg & 1;
    const int sblk = (seg >> 1) * 16;
    const int bbase = ((sblk + (p >> 3)) * 32 + (p & 7) * 4) * 2 + rsel;
    const __half* xc = xb + seg * 8;

    uint4 gr0, gr1, gr2, gr3;
    float4 gwv;

    auto gather_load = [&](int ck) {
        const int tap = ck >> 3;
        const int c0  = (ck & 7) * BKC;
        gwv = cw[tap * TILE_P + p];
        const ushort4 iv = ci[tap * TILE_P + p];
        const __half* xcc = xc + c0;
        gr0 = *reinterpret_cast<const uint4*>(xcc + (int)iv.x * CC);
        gr1 = *reinterpret_cast<const uint4*>(xcc + (int)iv.y * CC);
        gr2 = *reinterpret_cast<const uint4*>(xcc + (int)iv.z * CC);
        gr3 = *reinterpret_cast<const uint4*>(xcc + (int)iv.w * CC);
    };

    // store into buffer bufsel, chunk slot (0/1)
    auto gather_store = [&](int bufsel, int slot) {
        uint32_t* bb = reinterpret_cast<uint32_t*>(smem + SM_B + bufsel * 16384 + slot * 8192);
        const __half2 wx2 = __float2half2_rn(gwv.x);
        const __half2 wy2 = __float2half2_rn(gwv.y);
        const __half2 wz2 = __float2half2_rn(gwv.z);
        const __half2 ww2 = __float2half2_rn(gwv.w);
        const __half2* a0 = reinterpret_cast<const __half2*>(&gr0);
        const __half2* a1 = reinterpret_cast<const __half2*>(&gr1);
        const __half2* a2 = reinterpret_cast<const __half2*>(&gr2);
        const __half2* a3 = reinterpret_cast<const __half2*>(&gr3);
        #pragma unroll
        for (int j = 0; j < 4; j++) {
            __half2 s = __hmul2(wx2, a0[j]);
            s = __hfma2(wy2, a1[j], s);
            s = __hfma2(wz2, a2[j], s);
            s = __hfma2(ww2, a3[j], s);
            bb[bbase + j * 2] = *reinterpret_cast<const uint32_t*>(&s);
        }
    };

    // interval A prefetch: 32 KB (2 chunks), 512 threads x 64 B
    auto a_prefetch = [&](int j, int bufsel) {
        const uint32_t* src = g_wtf + (size_t)j * 8192 + tid * 16;
        const uint32_t dst = smem_u32(smem + SM_A + bufsel * 32768) + tid * 64;
        CP_ASYNC16(dst,      src);
        CP_ASYNC16(dst + 16, src + 4);
        CP_ASYNC16(dst + 32, src + 8);
        CP_ASYNC16(dst + 48, src + 12);
        CP_COMMIT();
    };

    const int warp_m = wid >> 2;   // 0..3 -> 64 output rows
    const int warp_n = wid & 3;    // 0..3 -> 32 pixels

    float acc[4][4][4];
    #pragma unroll
    for (int mf = 0; mf < 4; mf++)
        #pragma unroll
        for (int nf = 0; nf < 4; nf++)
            #pragma unroll
            for (int r = 0; r < 4; r++)
                acc[mf][nf][r] = 0.f;

    // MMA over one chunk resident in smem
    auto mma_chunk = [&](const uint32_t* Af, const uint32_t* Bf) {
        #pragma unroll
        for (int s = 0; s < 2; s++) {
            uint32_t a[4][4];
            uint32_t bq[4][2];
            #pragma unroll
            for (int mf = 0; mf < 4; mf++) {
                const uint4 v = reinterpret_cast<const uint4*>(Af)[(s * 16 + warp_m * 4 + mf) * 32 + lane];
                a[mf][0] = v.x; a[mf][1] = v.y; a[mf][2] = v.z; a[mf][3] = v.w;
            }
            #pragma unroll
            for (int nf = 0; nf < 4; nf++) {
                const uint2 v = reinterpret_cast<const uint2*>(Bf)[(s * 16 + warp_n * 4 + nf) * 32 + lane];
                bq[nf][0] = v.x; bq[nf][1] = v.y;
            }
            #pragma unroll
            for (int mf = 0; mf < 4; mf++)
                #pragma unroll
                for (int nf = 0; nf < 4; nf++)
                    mma_f16(acc[mf][nf], a[mf], bq[nf]);
        }
    };

    // ---- prologue: interval 0 into buffer 0
    a_prefetch(0, 0);
    __syncthreads();          // coefficients ready
    gather_load(0);
    gather_store(0, 0);
    gather_load(1);
    gather_store(0, 1);
    CP_WAIT0();
    __syncthreads();

    for (int j = 0; j < NINT; j++) {
        const int buf = j & 1;
        const bool more = (j + 1 < NINT);
        if (more) a_prefetch(j + 1, buf ^ 1);

        const uint32_t* Af = reinterpret_cast<const uint32_t*>(smem + SM_A + buf * 32768);
        const uint32_t* Bf = reinterpret_cast<const uint32_t*>(smem + SM_B + buf * 16384);

        if (more) gather_load(2 * j + 2);
        mma_chunk(Af, Bf);
        if (more) {
            gather_store(buf ^ 1, 0);
            gather_load(2 * j + 3);
        }
        mma_chunk(Af + 4096, Bf + 2048);
        if (more) gather_store(buf ^ 1, 1);

        CP_WAIT0();
        __syncthreads();
    }

    // ---- epilogue: direct float2 stores
    #pragma unroll
    for (int mf = 0; mf < 4; mf++) {
        const int o = warp_m * 64 + mf * 16 + (lane >> 2);
        float* r0 = out + ((size_t)(b * OO + o)) * PIXI + pimg0 + warp_n * 32 + (lane & 3) * 2;
        float* r1 = r0 + 8 * PIXI;
        #pragma unroll
        for (int nf = 0; nf < 4; nf++) {
            *reinterpret_cast<float2*>(r0 + nf * 8) = make_float2(acc[mf][nf][0], acc[mf][nf][1]);
            *reinterpret_cast<float2*>(r1 + nf * 8) = make_float2(acc[mf][nf][2], acc[mf][nf][3]);
        }
    }
}

// ---------------------------------------------------------------- launcher
extern "C" void kernel_launch(void* const* d_in, const int* in_sizes, int n_in,
                              void* d_out, int out_size) {
    const float* x      = (const float*)d_in[0];
    const float* offset = (const float*)d_in[1];
    const float* weight = (const float*)d_in[2];
    float* out          = (float*)d_out;

    cudaFuncSetAttribute(dfconv_main,
                         cudaFuncAttributeMaxDynamicSharedMemorySize, SMEM_SZ);

    prep_kernel<<<XBLKS + WBLKS, 256>>>(x, weight);
    dfconv_main<<<BB * (PIXI / TILE_P), NTH, SMEM_SZ>>>(offset, out);
}